// round 1
// baseline (speedup 1.0000x reference)
#include <cuda_runtime.h>
#include <cuda_bf16.h>

// SumGoalHistory: out_t = sigmoid(init + prefix_sum(goal, axis=T)), plus final
// state written twice after the outputs block.
// Shapes: goal [T=512, B=64, D=1024] fp32, init [1, 64, 1024] fp32.
// One thread per (b,d) column; sequential scan over T with unrolled loads.

#define T_DIM 512
#define BD    (64 * 1024)

__global__ __launch_bounds__(128, 8)
void SumGoalHistory_19387482374813_kernel(const float* __restrict__ goal,
                                          const float* __restrict__ init_state,
                                          float* __restrict__ out) {
    const int col = blockIdx.x * blockDim.x + threadIdx.x;  // 0 .. BD-1

    float acc = init_state[col];
    const float* g = goal + col;
    float*       o = out  + col;

    #pragma unroll 8
    for (int t = 0; t < T_DIM; t++) {
        acc += g[(size_t)t * BD];
        // fast sigmoid: 1 / (1 + exp(-x)) via MUFU EX2 + RCP
        float s = __fdividef(1.0f, 1.0f + __expf(-acc));
        o[(size_t)t * BD] = s;
    }

    // final_state, duplicated twice after the outputs block
    out[(size_t)T_DIM * BD + col]        = acc;
    out[(size_t)(T_DIM + 1) * BD + col]  = acc;
}

extern "C" void kernel_launch(void* const* d_in, const int* in_sizes, int n_in,
                              void* d_out, int out_size) {
    const float* goal = (const float*)d_in[0];
    const float* init = (const float*)d_in[1];
    float* out = (float*)d_out;

    dim3 grid(BD / 128);
    dim3 block(128);
    SumGoalHistory_19387482374813_kernel<<<grid, block>>>(goal, init, out);
}

// round 3
// speedup vs baseline: 1.3226x; 1.3226x over previous
#include <cuda_runtime.h>
#include <cuda_bf16.h>

// SumGoalHistory: out_t = sigmoid(init + prefix_sum(goal, axis=T)), final state x2.
// goal [T=512, B=64, D=1024] fp32, init [1,64,1024] fp32.
// One thread per (b,d) column. Software-pipelined: U=16 loads in flight while
// the previous batch's sigmoid+store epilogue executes -> ~4 MB chip-wide MLP.

#define T_DIM 512
#define BD    (64 * 1024)
#define U     16

__device__ __forceinline__ float fast_sigmoid(float x) {
    return __fdividef(1.0f, 1.0f + __expf(-x));
}

__global__ __launch_bounds__(128)
void SumGoalHistory_19387482374813_kernel(const float* __restrict__ goal,
                                          const float* __restrict__ init_state,
                                          float* __restrict__ out) {
    const int col = blockIdx.x * blockDim.x + threadIdx.x;  // 0 .. BD-1

    float acc = init_state[col];
    const float* g = goal + col;
    float*       o = out  + col;

    float buf[U];
    // Prime the pipeline: first batch of 16 independent loads.
    #pragma unroll
    for (int u = 0; u < U; u++)
        buf[u] = __ldcs(g + (size_t)u * BD);

    // Main loop: issue next batch's 16 loads, then consume current batch.
    for (int t0 = 0; t0 < T_DIM - U; t0 += U) {
        float nxt[U];
        #pragma unroll
        for (int u = 0; u < U; u++)
            nxt[u] = __ldcs(g + (size_t)(t0 + U + u) * BD);

        #pragma unroll
        for (int u = 0; u < U; u++) {
            acc += buf[u];
            __stcs(o + (size_t)(t0 + u) * BD, fast_sigmoid(acc));
        }

        #pragma unroll
        for (int u = 0; u < U; u++)
            buf[u] = nxt[u];
    }

    // Tail batch (no prefetch).
    #pragma unroll
    for (int u = 0; u < U; u++) {
        acc += buf[u];
        __stcs(o + (size_t)(T_DIM - U + u) * BD, fast_sigmoid(acc));
    }

    // final_state written twice after the outputs block
    __stcs(o + (size_t)T_DIM * BD,       acc);
    __stcs(o + (size_t)(T_DIM + 1) * BD, acc);
}

extern "C" void kernel_launch(void* const* d_in, const int* in_sizes, int n_in,
                              void* d_out, int out_size) {
    const float* goal = (const float*)d_in[0];
    const float* init = (const float*)d_in[1];
    float* out = (float*)d_out;

    SumGoalHistory_19387482374813_kernel<<<BD / 128, 128>>>(goal, init, out);
}